// round 5
// baseline (speedup 1.0000x reference)
#include <cuda_runtime.h>

// RNN_33964601377372: h_{t+1} = relu(x_t*W_ih + b_ih + b_hh + W_hh h_t), out = fc(h_T)
//
// Quad layout (4 lanes/batch, 5 rows/lane), j-packed f32x2 math, h exchanged
// through shared memory: each lane stores its 5 h scalars (conflict-free
// STS.32) and reloads all 20 h as 5x ld.shared.v2.u64 -> ready-made f32x2
// pairs, zero pack/dup instructions. 1-warp CTAs make __syncthreads the 3-cyc
// nw=1 BAR (which also drains STS), so one barrier per step is nearly free.

#define HID 20
#define QUAD 4

typedef unsigned long long u64;

__device__ __forceinline__ u64 pack2(float lo, float hi) {
    u64 r; asm("mov.b64 %0, {%1, %2};" : "=l"(r) : "f"(lo), "f"(hi)); return r;
}
__device__ __forceinline__ u64 dup2(float v) {
    u64 r; asm("mov.b64 %0, {%1, %1};" : "=l"(r) : "f"(v)); return r;
}
__device__ __forceinline__ void unpack2(u64 p, float& lo, float& hi) {
    asm("mov.b64 {%0, %1}, %2;" : "=f"(lo), "=f"(hi) : "l"(p));
}
__device__ __forceinline__ u64 ffma2(u64 a, u64 b, u64 c) {
    u64 d; asm("fma.rn.f32x2 %0, %1, %2, %3;" : "=l"(d) : "l"(a), "l"(b), "l"(c)); return d;
}
__device__ __forceinline__ void lds_v2u64(unsigned addr, u64& a, u64& b) {
    asm volatile("ld.shared.v2.u64 {%0, %1}, [%2];" : "=l"(a), "=l"(b) : "r"(addr));
}
__device__ __forceinline__ void sts_f32(unsigned addr, float v) {
    asm volatile("st.shared.f32 [%0], %1;" :: "r"(addr), "f"(v));
}

__global__ __launch_bounds__(32) void rnn_fused_kernel(
    const float* __restrict__ x,    // [B, T]
    const float* __restrict__ Wih,  // [H]
    const float* __restrict__ Whh,  // [H, H] row-major
    const float* __restrict__ bih,  // [H]
    const float* __restrict__ bhh,  // [H]
    const float* __restrict__ fcw,  // [H]
    const float* __restrict__ fcb,  // [1]
    float* __restrict__ out,        // [B]
    int B, int T)
{
    // 8 batches per 32-thread CTA; quad stride 20 floats (80B) is
    // bank-conflict-free for both the v2.u64 reads and the scalar writes.
    __shared__ float hbuf[8][HID];

    const int lane = threadIdx.x;      // 0..31
    const int quad = lane >> 2;        // 0..7 : batch within CTA
    const int e    = lane & 3;         // lane within quad: rows e*5 .. e*5+4
    int batch = blockIdx.x * 8 + quad;
    const bool real = (batch < B);
    if (!real) batch = B - 1;          // clamp; keep lane resident for BAR/shfl
    const int r0 = e * 5;

    // j-packed weights: wJ[r][k] = (Whh[r0+r][2k], Whh[r0+r][2k+1])
    u64 wJ[5][10];
#pragma unroll
    for (int r = 0; r < 5; ++r)
#pragma unroll
        for (int k = 0; k < 10; ++k)
            wJ[r][k] = pack2(Whh[(r0 + r) * HID + 2 * k],
                             Whh[(r0 + r) * HID + 2 * k + 1]);

    // x-projection packed into lo half: acc = ffma2(dup(xt), (wih,0), (bias,0))
    u64 wihP[5], biasP[5];
#pragma unroll
    for (int r = 0; r < 5; ++r) {
        wihP[r]  = pack2(Wih[r0 + r], 0.0f);
        biasP[r] = pack2(bih[r0 + r] + bhh[r0 + r], 0.0f);
    }

    const unsigned sbase =
        (unsigned)__cvta_generic_to_shared(&hbuf[quad][0]);  // 16B-aligned
    const unsigned swr = sbase + 4u * (unsigned)r0;          // my 5 rows

    // h(0) = 0
#pragma unroll
    for (int r = 0; r < 5; ++r) sts_f32(swr + 4u * r, 0.0f);
    __syncthreads();

    float h[5];                        // my rows' latest values (for the head)
#pragma unroll
    for (int r = 0; r < 5; ++r) h[r] = 0.0f;

    const float* xb = x + (size_t)batch * T;   // 4000B stride, 16B-aligned
    const float4* xb4 = (const float4*)xb;
    const int nChunks = T >> 2;

    float4 xv = (nChunks > 0) ? xb4[0] : make_float4(0.f, 0.f, 0.f, 0.f);
    float4 xnext = xv;

    for (int c = 0; c < nChunks; ++c) {
        if (c + 1 < nChunks) xnext = xb4[c + 1];  // 4 steps of load hiding
#pragma unroll
        for (int s = 0; s < 4; ++s) {
            float xt = (s == 0) ? xv.x : (s == 1) ? xv.y : (s == 2) ? xv.z : xv.w;

            // 5 vector loads deliver all 20 h as 10 ready f32x2 pairs.
            u64 hp[10];
#pragma unroll
            for (int i = 0; i < 5; ++i)
                lds_v2u64(sbase + 16u * i, hp[2 * i], hp[2 * i + 1]);

            u64 xt2 = dup2(xt);
            u64 acc[5];
#pragma unroll
            for (int r = 0; r < 5; ++r)
                acc[r] = ffma2(xt2, wihP[r], biasP[r]);

#pragma unroll
            for (int k = 0; k < 10; ++k)
#pragma unroll
                for (int r = 0; r < 5; ++r)
                    acc[r] = ffma2(hp[k], wJ[r][k], acc[r]);

#pragma unroll
            for (int r = 0; r < 5; ++r) {
                float lo, hi;
                unpack2(acc[r], lo, hi);
                h[r] = fmaxf(lo + hi, 0.0f);
                sts_f32(swr + 4u * r, h[r]);
            }
            __syncthreads();   // nw=1 BAR: 3 cyc + STS drain
        }
        xv = xnext;
    }

    // Scalar tail (not taken for T=1000).
    for (int t = nChunks << 2; t < T; ++t) {
        float xt = xb[t];
        u64 hp[10];
#pragma unroll
        for (int i = 0; i < 5; ++i)
            lds_v2u64(sbase + 16u * i, hp[2 * i], hp[2 * i + 1]);
        u64 xt2 = dup2(xt);
        u64 acc[5];
#pragma unroll
        for (int r = 0; r < 5; ++r)
            acc[r] = ffma2(xt2, wihP[r], biasP[r]);
#pragma unroll
        for (int k = 0; k < 10; ++k)
#pragma unroll
            for (int r = 0; r < 5; ++r)
                acc[r] = ffma2(hp[k], wJ[r][k], acc[r]);
#pragma unroll
        for (int r = 0; r < 5; ++r) {
            float lo, hi;
            unpack2(acc[r], lo, hi);
            h[r] = fmaxf(lo + hi, 0.0f);
            sts_f32(swr + 4u * r, h[r]);
        }
        __syncthreads();
    }

    // Head: out[b] = h . fc_w + fc_b ; quad butterfly reduction.
    float p = 0.0f;
#pragma unroll
    for (int r = 0; r < 5; ++r) p = fmaf(h[r], fcw[r0 + r], p);
    p += __shfl_xor_sync(0xffffffffu, p, 1, QUAD);
    p += __shfl_xor_sync(0xffffffffu, p, 2, QUAD);
    if (e == 0 && real) out[batch] = p + fcb[0];
}

extern "C" void kernel_launch(void* const* d_in, const int* in_sizes, int n_in,
                              void* d_out, int out_size)
{
    const float* x    = (const float*)d_in[0];
    const float* Wih  = (const float*)d_in[1];
    const float* Whh  = (const float*)d_in[2];
    const float* bih  = (const float*)d_in[3];
    const float* bhh  = (const float*)d_in[4];
    const float* fcw  = (const float*)d_in[5];
    const float* fcb  = (const float*)d_in[6];
    float* out = (float*)d_out;

    int B = out_size;
    int T = in_sizes[0] / B;

    const int threads = 32;                    // 1 warp per CTA, 8 batches
    int blocks = (B + 7) / 8;                  // 512 CTAs at B=4096
    rnn_fused_kernel<<<blocks, threads>>>(x, Wih, Whh, bih, bhh, fcw, fcb, out, B, T);
}

// round 6
// speedup vs baseline: 1.0685x; 1.0685x over previous
#include <cuda_runtime.h>

// RNN_33964601377372: h_{t+1} = relu(x_t*W_ih + b_ih + b_hh + W_hh h_t), out = fc(h_T)
//
// Quad layout (4 lanes/batch, 5 rows/lane), j-packed f32x2 math (R4 body).
// KEY CHANGE vs R4: block=128 so the CTA's 4 warps land one per SMSP
// (wid%4 placement). 128 CTAs -> 1 CTA/SM, 1 warp/SMSP: per-step cost is
// max(fma-pipe 60*2, issue ~100, dep-chain ~90) ~ 120-130 cyc instead of
// 2 warps time-slicing one scheduler (~210+).

#define HID 20
#define QUAD 4

typedef unsigned long long u64;

__device__ __forceinline__ u64 pack2(float lo, float hi) {
    u64 r; asm("mov.b64 %0, {%1, %2};" : "=l"(r) : "f"(lo), "f"(hi)); return r;
}
__device__ __forceinline__ u64 dup2(float v) {
    u64 r; asm("mov.b64 %0, {%1, %1};" : "=l"(r) : "f"(v)); return r;
}
__device__ __forceinline__ void unpack2(u64 p, float& lo, float& hi) {
    asm("mov.b64 {%0, %1}, %2;" : "=f"(lo), "=f"(hi) : "l"(p));
}
__device__ __forceinline__ u64 ffma2(u64 a, u64 b, u64 c) {
    u64 d; asm("fma.rn.f32x2 %0, %1, %2, %3;" : "=l"(d) : "l"(a), "l"(b), "l"(c)); return d;
}

__global__ __launch_bounds__(128) void rnn_fused_kernel(
    const float* __restrict__ x,    // [B, T]
    const float* __restrict__ Wih,  // [H]
    const float* __restrict__ Whh,  // [H, H] row-major
    const float* __restrict__ bih,  // [H]
    const float* __restrict__ bhh,  // [H]
    const float* __restrict__ fcw,  // [H]
    const float* __restrict__ fcb,  // [1]
    float* __restrict__ out,        // [B]
    int B, int T)
{
    int tid = blockIdx.x * blockDim.x + threadIdx.x;
    int batch = tid >> 2;
    int q = tid & 3;           // lane within quad: owns rows q*5 .. q*5+4
    if (batch >= B) return;
    const int r0 = q * 5;

    // j-packed weights: wJ[r][k] = (Whh[r0+r][2k], Whh[r0+r][2k+1])
    u64 wJ[5][10];
#pragma unroll
    for (int r = 0; r < 5; ++r)
#pragma unroll
        for (int k = 0; k < 10; ++k)
            wJ[r][k] = pack2(Whh[(r0 + r) * HID + 2 * k],
                             Whh[(r0 + r) * HID + 2 * k + 1]);

    // x-projection packed into lo half: acc = ffma2(dup(xt), (wih,0), (bias,0))
    u64 wihP[5], biasP[5];
#pragma unroll
    for (int r = 0; r < 5; ++r) {
        wihP[r]  = pack2(Wih[r0 + r], 0.0f);
        biasP[r] = pack2(bih[r0 + r] + bhh[r0 + r], 0.0f);
    }

    float h[5];
#pragma unroll
    for (int r = 0; r < 5; ++r) h[r] = 0.0f;

    const float* xb = x + (size_t)batch * T;   // 4000B stride, 16B-aligned
    const float4* xb4 = (const float4*)xb;
    const int nChunks = T >> 2;

    float4 xv = (nChunks > 0) ? xb4[0] : make_float4(0.f, 0.f, 0.f, 0.f);
    float4 xnext = xv;

    for (int c = 0; c < nChunks; ++c) {
        if (c + 1 < nChunks) xnext = xb4[c + 1];  // 4 steps of load hiding
#pragma unroll
        for (int s = 0; s < 4; ++s) {
            float xt = (s == 0) ? xv.x : (s == 1) ? xv.y : (s == 2) ? xv.z : xv.w;

            // Broadcast all 20 h within the quad; x-proj FFMA2s below fill
            // the shuffle-latency window.
            float hj[HID];
#pragma unroll
            for (int j = 0; j < HID; ++j)
                hj[j] = __shfl_sync(0xffffffffu, h[j % 5], j / 5, QUAD);

            u64 xt2 = dup2(xt);
            u64 acc[5];
#pragma unroll
            for (int r = 0; r < 5; ++r)
                acc[r] = ffma2(xt2, wihP[r], biasP[r]);

#pragma unroll
            for (int k = 0; k < 10; ++k) {
                u64 p = pack2(hj[2 * k], hj[2 * k + 1]);
#pragma unroll
                for (int r = 0; r < 5; ++r)
                    acc[r] = ffma2(p, wJ[r][k], acc[r]);
            }
#pragma unroll
            for (int r = 0; r < 5; ++r) {
                float lo, hi;
                unpack2(acc[r], lo, hi);
                h[r] = fmaxf(lo + hi, 0.0f);
            }
        }
        xv = xnext;
    }

    // Scalar tail (not taken for T=1000).
    for (int t = nChunks << 2; t < T; ++t) {
        float xt = xb[t];
        float hj[HID];
#pragma unroll
        for (int j = 0; j < HID; ++j)
            hj[j] = __shfl_sync(0xffffffffu, h[j % 5], j / 5, QUAD);
        u64 xt2 = dup2(xt);
        u64 acc[5];
#pragma unroll
        for (int r = 0; r < 5; ++r)
            acc[r] = ffma2(xt2, wihP[r], biasP[r]);
#pragma unroll
        for (int k = 0; k < 10; ++k) {
            u64 p = pack2(hj[2 * k], hj[2 * k + 1]);
#pragma unroll
            for (int r = 0; r < 5; ++r)
                acc[r] = ffma2(p, wJ[r][k], acc[r]);
        }
#pragma unroll
        for (int r = 0; r < 5; ++r) {
            float lo, hi;
            unpack2(acc[r], lo, hi);
            h[r] = fmaxf(lo + hi, 0.0f);
        }
    }

    // Head: out[b] = h . fc_w + fc_b ; quad butterfly reduction.
    float p = 0.0f;
#pragma unroll
    for (int r = 0; r < 5; ++r) p = fmaf(h[r], fcw[r0 + r], p);
    p += __shfl_xor_sync(0xffffffffu, p, 1, QUAD);
    p += __shfl_xor_sync(0xffffffffu, p, 2, QUAD);
    if (q == 0) out[batch] = p + fcb[0];
}

extern "C" void kernel_launch(void* const* d_in, const int* in_sizes, int n_in,
                              void* d_out, int out_size)
{
    const float* x    = (const float*)d_in[0];
    const float* Wih  = (const float*)d_in[1];
    const float* Whh  = (const float*)d_in[2];
    const float* bih  = (const float*)d_in[3];
    const float* bhh  = (const float*)d_in[4];
    const float* fcw  = (const float*)d_in[5];
    const float* fcb  = (const float*)d_in[6];
    float* out = (float*)d_out;

    int B = out_size;
    int T = in_sizes[0] / B;

    const int threads = 128;              // 4 warps/CTA -> one per SMSP
    int total = B * QUAD;                 // 16384 lanes
    int blocks = (total + threads - 1) / threads;  // 128 CTAs at B=4096
    rnn_fused_kernel<<<blocks, threads>>>(x, Wih, Whh, bih, bhh, fcw, fcb, out, B, T);
}

// round 7
// speedup vs baseline: 1.1344x; 1.0616x over previous
#include <cuda_runtime.h>

// RNN_33964601377372: h_{t+1} = relu(x_t*W_ih + b_ih + b_hh + W_hh h_t), out = fc(h_T)
//
// Quad layout (4 lanes/batch, 5 rows/lane). h exchanged via per-warp shared
// memory with parity double-buffering: each step is STS(5) -> syncwarp ->
// LDS.128(5) giving 10 ready f32x2 pairs (zero pack/dup instrs). Each row's
// 10-pair dot product runs as TWO 5-deep FFMA2 chains combined by FADD2
// (critical path 6 fma ops, 10 independent chains). block=128 puts the 4
// warps one per SMSP; 128 CTAs = 1 CTA/SM.

#define HID 20
#define QUAD 4

typedef unsigned long long u64;

__device__ __forceinline__ u64 pack2(float lo, float hi) {
    u64 r; asm("mov.b64 %0, {%1, %2};" : "=l"(r) : "f"(lo), "f"(hi)); return r;
}
__device__ __forceinline__ u64 dup2(float v) {
    u64 r; asm("mov.b64 %0, {%1, %1};" : "=l"(r) : "f"(v)); return r;
}
__device__ __forceinline__ void unpack2(u64 p, float& lo, float& hi) {
    asm("mov.b64 {%0, %1}, %2;" : "=f"(lo), "=f"(hi) : "l"(p));
}
__device__ __forceinline__ u64 ffma2(u64 a, u64 b, u64 c) {
    u64 d; asm("fma.rn.f32x2 %0, %1, %2, %3;" : "=l"(d) : "l"(a), "l"(b), "l"(c)); return d;
}
__device__ __forceinline__ u64 fmul2(u64 a, u64 b) {
    u64 d; asm("mul.rn.f32x2 %0, %1, %2;" : "=l"(d) : "l"(a), "l"(b)); return d;
}
__device__ __forceinline__ u64 fadd2(u64 a, u64 b) {
    u64 d; asm("add.rn.f32x2 %0, %1, %2;" : "=l"(d) : "l"(a), "l"(b)); return d;
}
__device__ __forceinline__ void lds_v2u64(unsigned addr, u64& a, u64& b) {
    asm volatile("ld.shared.v2.u64 {%0, %1}, [%2];" : "=l"(a), "=l"(b) : "r"(addr));
}
__device__ __forceinline__ void sts_f32(unsigned addr, float v) {
    asm volatile("st.shared.f32 [%0], %1;" :: "r"(addr), "f"(v));
}

__global__ __launch_bounds__(128) void rnn_fused_kernel(
    const float* __restrict__ x,    // [B, T]
    const float* __restrict__ Wih,  // [H]
    const float* __restrict__ Whh,  // [H, H] row-major
    const float* __restrict__ bih,  // [H]
    const float* __restrict__ bhh,  // [H]
    const float* __restrict__ fcw,  // [H]
    const float* __restrict__ fcb,  // [1]
    float* __restrict__ out,        // [B]
    int B, int T)
{
    // [parity][quad][row]; quad stride 80B is conflict-free for both the
    // 16B broadcast reads (8 addrs/warp -> 32 distinct banks) and the
    // scattered STS.32 writes (32 distinct words mod 32).
    __shared__ float hbuf[2][32][HID];

    const int lt   = threadIdx.x;
    const int quad = lt >> 2;          // 0..31 (8 per warp)
    const int e    = lt & 3;           // lane in quad: rows e*5 .. e*5+4
    int batch = blockIdx.x * 32 + quad;
    const bool real = (batch < B);
    if (!real) batch = B - 1;          // clamp; lane stays resident
    const int r0 = e * 5;

    // j-packed weights: wJ[r][k] = (Whh[r0+r][2k], Whh[r0+r][2k+1])
    u64 wJ[5][10];
#pragma unroll
    for (int r = 0; r < 5; ++r)
#pragma unroll
        for (int k = 0; k < 10; ++k)
            wJ[r][k] = pack2(Whh[(r0 + r) * HID + 2 * k],
                             Whh[(r0 + r) * HID + 2 * k + 1]);

    // x-projection folded into chain A's seed: ffma2(dup(xt),(wih,0),(bias,0))
    u64 wihP[5], biasP[5];
#pragma unroll
    for (int r = 0; r < 5; ++r) {
        wihP[r]  = pack2(Wih[r0 + r], 0.0f);
        biasP[r] = pack2(bih[r0 + r] + bhh[r0 + r], 0.0f);
    }

    const unsigned sA = (unsigned)__cvta_generic_to_shared(&hbuf[0][quad][0]);
    const unsigned sB = (unsigned)__cvta_generic_to_shared(&hbuf[1][quad][0]);

    // h(0) = 0 into buffer 0 (step 0 reads parity 0).
#pragma unroll
    for (int r = 0; r < 5; ++r) sts_f32(sA + 4u * (r0 + r), 0.0f);
    __syncwarp();

    float h[5];
#pragma unroll
    for (int r = 0; r < 5; ++r) h[r] = 0.0f;

    const float* xb = x + (size_t)batch * T;    // 4000B stride, 16B-aligned
    const float4* xb4 = (const float4*)xb;
    const int nChunks = T >> 2;

    float4 xv = (nChunks > 0) ? xb4[0] : make_float4(0.f, 0.f, 0.f, 0.f);
    float4 xnext = xv;

    // One step: read h pairs from rd, compute, write new h to wr.
    auto step = [&](float xt, unsigned rd, unsigned wr) {
        u64 xt2 = dup2(xt);
        u64 accA[5], accB[5];
#pragma unroll
        for (int r = 0; r < 5; ++r)
            accA[r] = ffma2(xt2, wihP[r], biasP[r]);  // independent of LDS

        __syncwarp();                   // order prev STS before these LDS
        u64 hp[10];
#pragma unroll
        for (int i = 0; i < 5; ++i)
            lds_v2u64(rd + 16u * i, hp[2 * i], hp[2 * i + 1]);

#pragma unroll
        for (int r = 0; r < 5; ++r)
            accB[r] = fmul2(hp[5], wJ[r][5]);
#pragma unroll
        for (int k = 0; k < 5; ++k)
#pragma unroll
            for (int r = 0; r < 5; ++r)
                accA[r] = ffma2(hp[k], wJ[r][k], accA[r]);
#pragma unroll
        for (int k = 6; k < 10; ++k)
#pragma unroll
            for (int r = 0; r < 5; ++r)
                accB[r] = ffma2(hp[k], wJ[r][k], accB[r]);

#pragma unroll
        for (int r = 0; r < 5; ++r) {
            u64 s = fadd2(accA[r], accB[r]);
            float lo, hi;
            unpack2(s, lo, hi);
            h[r] = fmaxf(lo + hi, 0.0f);
            sts_f32(wr + 4u * (r0 + r), h[r]);
        }
    };

    for (int c = 0; c < nChunks; ++c) {
        if (c + 1 < nChunks) xnext = xb4[c + 1];  // 4 steps of load hiding
        step(xv.x, sA, sB);
        step(xv.y, sB, sA);
        step(xv.z, sA, sB);
        step(xv.w, sB, sA);
        xv = xnext;
    }

    // Scalar tail (not taken for T=1000); parity continues from even count.
    for (int t = nChunks << 2; t < T; ++t) {
        if (t & 1) step(xb[t], sB, sA);
        else       step(xb[t], sA, sB);
    }

    // Head: out[b] = h . fc_w + fc_b ; quad butterfly reduction.
    float p = 0.0f;
#pragma unroll
    for (int r = 0; r < 5; ++r) p = fmaf(h[r], fcw[r0 + r], p);
    p += __shfl_xor_sync(0xffffffffu, p, 1, QUAD);
    p += __shfl_xor_sync(0xffffffffu, p, 2, QUAD);
    if (e == 0 && real) out[batch] = p + fcb[0];
}

extern "C" void kernel_launch(void* const* d_in, const int* in_sizes, int n_in,
                              void* d_out, int out_size)
{
    const float* x    = (const float*)d_in[0];
    const float* Wih  = (const float*)d_in[1];
    const float* Whh  = (const float*)d_in[2];
    const float* bih  = (const float*)d_in[3];
    const float* bhh  = (const float*)d_in[4];
    const float* fcw  = (const float*)d_in[5];
    const float* fcb  = (const float*)d_in[6];
    float* out = (float*)d_out;

    int B = out_size;
    int T = in_sizes[0] / B;

    const int threads = 128;              // 4 warps -> one per SMSP; 32 batches/CTA
    int blocks = (B + 31) / 32;           // 128 CTAs at B=4096
    rnn_fused_kernel<<<blocks, threads>>>(x, Wih, Whh, bih, bhh, fcw, fcb, out, B, T);
}